// round 16
// baseline (speedup 1.0000x reference)
#include <cuda_runtime.h>
#include <cuda_fp16.h>
#include <cstdint>

#define NN 100000
#define NE 600000
#define DD 128
#define NBLK 98                         // ceil(NN/1024)
#define NGRP 6250                       // NN/16 row groups
#define NTILE 1563                      // ceil(NN/64) gemm M-tiles
#define GGRID 444                       // 148 SMs x 3 CTAs persistent

// ---------------- scratch (device globals; no allocations allowed) ----------
static __device__ int   g_is64;
static __device__ int   g_deg[NN];
static __device__ float g_dinv[NN];
static __device__ int   g_off[NN + 1];
static __device__ int   g_cur[NN];
static __device__ int   g_col[NE];
static __device__ int   g_bsum[NBLK];
static __device__ __align__(16) unsigned long long g_Wimg[4096]; // 32KB W fp16 image
static __device__ __align__(16) uint4 g_HsF[NGRP * 8 * 32];      // 25.6MB fp16 A frags
static __device__ __align__(16) unsigned int g_Hlh[(long long)NN * 64]; // 25.6MB Hl fp16

typedef unsigned long long u64;
typedef unsigned int u32;

__device__ __forceinline__ int edge_at(const int* ei, int is64, int which, int e) {
    if (is64) {
        const long long* p = (const long long*)ei;
        return (int)p[(long long)which * NE + e];
    }
    return ei[which * NE + e];
}

__device__ __forceinline__ u32 pkh(float x, float y) {
    __half2 h = __floats2half2_rn(x, y);
    return *reinterpret_cast<u32*>(&h);
}

// ---------------- chain A-1) zero degrees + dtype sniff ----------------------
__global__ void k_prep(const int* __restrict__ ei) {
    int i = blockIdx.x * blockDim.x + threadIdx.x;
    if (i < NN) g_deg[i] = 0;
    if (blockIdx.x == 0) {
        __shared__ int nz;
        if (threadIdx.x == 0) nz = 0;
        __syncthreads();
        int acc = 0;
        for (int j = threadIdx.x; j < 1024; j += blockDim.x)
            acc |= ei[2 * j + 1];           // odd words all-zero <=> int64
        if (acc) atomicOr(&nz, 1);
        __syncthreads();
        if (threadIdx.x == 0) g_is64 = (nz == 0) ? 1 : 0;
    }
}

// ---------------- chain B-1) W -> fp16 swizzled smem image -------------------
__global__ void k_wsplit(const float* __restrict__ W) {
    int i = blockIdx.x * blockDim.x + threadIdx.x;
    if (i >= 4096) return;
    int n = i >> 5, kq = i & 31;
    float4 w = reinterpret_cast<const float4*>(W)[n * 32 + kq];
    u64 v = (u64)pkh(w.x, w.y) | ((u64)pkh(w.z, w.w) << 32);
    int off = n * 256 + (((kq >> 1) ^ (n & 7)) << 4) + (kq & 1) * 8;
    *reinterpret_cast<u64*>(reinterpret_cast<char*>(g_Wimg) + off) = v;
}

// ---------------- chain B-2) H -> fragment-ordered fp16 plane ----------------
__global__ void k_hsplit(const float* __restrict__ H) {
    int i = blockIdx.x * 256 + threadIdx.x;        // NGRP*8*32 = 1.6M exactly
    int lane = i & 31, ks = (i >> 5) & 7, m = i >> 8;
    int g = lane >> 2, tig = lane & 3;
    const float2* H2 = reinterpret_cast<const float2*>(H);
    long long ra = (long long)(m * 16 + g) * 64;
    long long rb = ra + 8 * 64;
    int c0 = ks * 8 + tig, c1 = c0 + 4;
    float2 x0 = H2[ra + c0];
    float2 x1 = H2[rb + c0];
    float2 x2 = H2[ra + c1];
    float2 x3 = H2[rb + c1];
    uint4 f;
    f.x = pkh(x0.x, x0.y);
    f.y = pkh(x1.x, x1.y);
    f.z = pkh(x2.x, x2.y);
    f.w = pkh(x3.x, x3.y);
    g_HsF[i] = f;
}

// ---------------- chain A-2) degree count ------------------------------------
__global__ void k_count(const int* __restrict__ ei) {
    int e = blockIdx.x * blockDim.x + threadIdx.x;
    if (e < NE) {
        int is64 = g_is64;
        int dst = edge_at(ei, is64, 0, e);
        if ((unsigned)dst < NN) atomicAdd(&g_deg[dst], 1);
    }
}

// ======== chain B-3) PERSISTENT GEMM, software-pipelined A loads =============
// Hl(fp16) = H @ W^T + b.  Per-tile: M=64 x N=128 x K=128; warps 2(M) x 4(N).
// A frags double-buffered: LDG for ks+1 issued before mma of ks.

#define SM_TOT 32768                    // W fp16 image

__device__ __forceinline__ void ldsm_x4(u32& r0, u32& r1, u32& r2, u32& r3, u32 addr) {
    asm volatile("ldmatrix.sync.aligned.m8n8.x4.shared.b16 {%0,%1,%2,%3}, [%4];"
                 : "=r"(r0), "=r"(r1), "=r"(r2), "=r"(r3) : "r"(addr));
}

__device__ __forceinline__ void mma_f16(float* d, const u32* a, const u32* b) {
    asm volatile("mma.sync.aligned.m16n8k16.row.col.f32.f16.f16.f32 "
                 "{%0,%1,%2,%3}, {%4,%5,%6,%7}, {%8,%9}, {%0,%1,%2,%3};"
                 : "+f"(d[0]), "+f"(d[1]), "+f"(d[2]), "+f"(d[3])
                 : "r"(a[0]), "r"(a[1]), "r"(a[2]), "r"(a[3]),
                   "r"(b[0]), "r"(b[1]));
}

__global__ void __launch_bounds__(256, 3)
k_gemm(const float* __restrict__ B) {
    extern __shared__ char smem[];
    const u32 smem_u32 = (u32)__cvta_generic_to_shared(smem);

    int t = threadIdx.x;

    // ---- stage B once: 32KB copy of precomputed image ----
    {
        const float4* src = reinterpret_cast<const float4*>(g_Wimg);
        float4* dst = reinterpret_cast<float4*>(smem);
#pragma unroll
        for (int i = 0; i < 8; i++)
            dst[t + 256 * i] = src[t + 256 * i];
    }
    __syncthreads();

    int w  = t >> 5;
    int l  = t & 31;
    int wm = w & 1;                     // M half
    int wn = w >> 1;                    // N quarter

    int rowB0 = wn * 32 + (l & 7) + ((l & 16) >> 1);
    int uB_add = ((l >> 3) & 1);
    int rq = l >> 2, cq = (l & 3) * 2;

    for (int tile = blockIdx.x; tile < NTILE; tile += GGRID) {
        int r0 = tile * 64;

        const uint4* pF[2];
#pragma unroll
        for (int mt = 0; mt < 2; mt++) {
            int gm = tile * 4 + wm * 2 + mt;
            if (gm >= NGRP) gm = NGRP - 1;
            pF[mt] = g_HsF + gm * 256 + l;
        }

        float d[2][4][4];
#pragma unroll
        for (int a = 0; a < 2; a++)
#pragma unroll
            for (int bq = 0; bq < 4; bq++)
#pragma unroll
                for (int c = 0; c < 4; c++) d[a][bq][c] = 0.0f;

        // software pipeline: prefetch ks=0, then overlap LDG(ks+1) with mma(ks)
        uint4 aF[2][2];                 // [parity][mt]
#pragma unroll
        for (int mt = 0; mt < 2; mt++)
            aF[0][mt] = pF[mt][0];

#pragma unroll
        for (int ks = 0; ks < 8; ks++) {
            int cur = ks & 1;
            if (ks < 7) {
#pragma unroll
                for (int mt = 0; mt < 2; mt++)
                    aF[cur ^ 1][mt] = pF[mt][(ks + 1) * 32];
            }
            u32 bF[2][4];
#pragma unroll
            for (int nt = 0; nt < 2; nt++) {
                int row = rowB0 + nt * 16;
                int u = 2 * ks + uB_add;
                u32 off = row * 256 + (((u) ^ (row & 7)) << 4);
                ldsm_x4(bF[nt][0], bF[nt][1], bF[nt][2], bF[nt][3], smem_u32 + off);
            }
#pragma unroll
            for (int mt = 0; mt < 2; mt++)
#pragma unroll
                for (int nt = 0; nt < 2; nt++)
#pragma unroll
                    for (int h = 0; h < 2; h++)
                        mma_f16(d[mt][nt * 2 + h],
                                reinterpret_cast<const u32*>(&aF[cur][mt]), &bF[nt][h * 2]);
        }

        // ---- epilogue: add bias, store fp16 ----
#pragma unroll
        for (int j = 0; j < 4; j++) {
            int col = wn * 32 + j * 8 + cq;
            float2 bias = *reinterpret_cast<const float2*>(B + col);
            int cp = col >> 1;
#pragma unroll
            for (int mt = 0; mt < 2; mt++) {
                int gr0 = r0 + wm * 32 + mt * 16 + rq;
                float* dd = d[mt][j];
                if (gr0 < NN)
                    g_Hlh[(long long)gr0 * 64 + cp] = pkh(dd[0] + bias.x, dd[1] + bias.y);
                if (gr0 + 8 < NN)
                    g_Hlh[(long long)(gr0 + 8) * 64 + cp] = pkh(dd[2] + bias.x, dd[3] + bias.y);
            }
        }
    }
}

// ---------------- chain A-3) per-block scan ----------------------------------
__global__ void k_blkscan() {
    __shared__ int ws[32];
    int t   = threadIdx.x;
    int i   = blockIdx.x * 1024 + t;
    int lane = t & 31, wid = t >> 5;

    int d = (i < NN) ? g_deg[i] : 0;

    int incl = d;
#pragma unroll
    for (int o = 1; o < 32; o <<= 1) {
        int v = __shfl_up_sync(0xffffffffu, incl, o);
        if (lane >= o) incl += v;
    }
    if (lane == 31) ws[wid] = incl;
    __syncthreads();
    if (wid == 0) {
        int v = ws[lane];
        int s = v;
#pragma unroll
        for (int o = 1; o < 32; o <<= 1) {
            int u = __shfl_up_sync(0xffffffffu, s, o);
            if (lane >= o) s += u;
        }
        ws[lane] = s - v;
    }
    __syncthreads();

    int excl = incl - d + ws[wid];
    if (i < NN) {
        g_off[i]  = excl;
        g_dinv[i] = rsqrtf((float)(d + 1));
    }
    if (t == 1023) g_bsum[blockIdx.x] = excl + d;
}

// ---------------- chain A-4) apply block offsets -----------------------------
__global__ void k_apply() {
    __shared__ int sb[NBLK];
    __shared__ int s_off;
    int t = threadIdx.x, bid = blockIdx.x;
    if (t < NBLK) sb[t] = g_bsum[t];
    __syncthreads();
    if (t == 0) {
        int run = 0;
        for (int b = 0; b < bid; b++) run += sb[b];
        s_off = run;
        if (bid == NBLK - 1) {
            int tot = run;
            for (int b = bid; b < NBLK; b++) tot += sb[b];
            g_off[NN] = tot;
        }
    }
    __syncthreads();
    int i = bid * 1024 + t;
    if (i < NN) {
        int v = g_off[i] + s_off;
        g_off[i] = v;
        g_cur[i] = v;
    }
}

// ---------------- chain A-5) CSR fill ----------------------------------------
__global__ void k_fill(const int* __restrict__ ei) {
    int e = blockIdx.x * blockDim.x + threadIdx.x;
    if (e < NE) {
        int is64 = g_is64;
        int dst = edge_at(ei, is64, 0, e);
        int src = edge_at(ei, is64, 1, e);
        if ((unsigned)dst < NN && (unsigned)src < NN) {
            int p = atomicAdd(&g_cur[dst], 1);
            if ((unsigned)p < NE) g_col[p] = src;
        }
    }
}

// ---------------- join) gather (fp16 src), 4-wide ILP ------------------------
__global__ void k_gather(float* __restrict__ out) {
    int gwarp = (blockIdx.x * blockDim.x + threadIdx.x) >> 5;
    int lane  = threadIdx.x & 31;
    if (gwarp >= NN) return;
    int i = gwarp;

    float di = g_dinv[i];
    const uint2* Hl = reinterpret_cast<const uint2*>(g_Hlh);

    float s2 = di * di;
    uint2 p = Hl[(long long)i * 32 + lane];
    float2 a0 = __half22float2(*reinterpret_cast<__half2*>(&p.x));
    float2 a1 = __half22float2(*reinterpret_cast<__half2*>(&p.y));
    float4 acc;
    acc.x = a0.x * s2; acc.y = a0.y * s2; acc.z = a1.x * s2; acc.w = a1.y * s2;

    int s = g_off[i];
    int e = g_off[i + 1];
    int j = s;
    for (; j + 3 < e; j += 4) {         // 4 independent L2 row streams
        int s0 = g_col[j];
        int s1 = g_col[j + 1];
        int s2i = g_col[j + 2];
        int s3 = g_col[j + 3];
        float n0 = di * g_dinv[s0];
        float n1 = di * g_dinv[s1];
        float n2 = di * g_dinv[s2i];
        float n3 = di * g_dinv[s3];
        uint2 p0 = Hl[(long long)s0 * 32 + lane];
        uint2 p1 = Hl[(long long)s1 * 32 + lane];
        uint2 p2 = Hl[(long long)s2i * 32 + lane];
        uint2 p3 = Hl[(long long)s3 * 32 + lane];
        float2 v00 = __half22float2(*reinterpret_cast<__half2*>(&p0.x));
        float2 v01 = __half22float2(*reinterpret_cast<__half2*>(&p0.y));
        float2 v10 = __half22float2(*reinterpret_cast<__half2*>(&p1.x));
        float2 v11 = __half22float2(*reinterpret_cast<__half2*>(&p1.y));
        float2 v20 = __half22float2(*reinterpret_cast<__half2*>(&p2.x));
        float2 v21 = __half22float2(*reinterpret_cast<__half2*>(&p2.y));
        float2 v30 = __half22float2(*reinterpret_cast<__half2*>(&p3.x));
        float2 v31 = __half22float2(*reinterpret_cast<__half2*>(&p3.y));
        acc.x += v00.x * n0; acc.y += v00.y * n0;
        acc.z += v01.x * n0; acc.w += v01.y * n0;
        acc.x += v10.x * n1; acc.y += v10.y * n1;
        acc.z += v11.x * n1; acc.w += v11.y * n1;
        acc.x += v20.x * n2; acc.y += v20.y * n2;
        acc.z += v21.x * n2; acc.w += v21.y * n2;
        acc.x += v30.x * n3; acc.y += v30.y * n3;
        acc.z += v31.x * n3; acc.w += v31.y * n3;
    }
    for (; j < e; j++) {
        int s0 = g_col[j];
        float n0 = di * g_dinv[s0];
        uint2 p0 = Hl[(long long)s0 * 32 + lane];
        float2 v00 = __half22float2(*reinterpret_cast<__half2*>(&p0.x));
        float2 v01 = __half22float2(*reinterpret_cast<__half2*>(&p0.y));
        acc.x += v00.x * n0; acc.y += v00.y * n0;
        acc.z += v01.x * n0; acc.w += v01.y * n0;
    }

    acc.x = fmaxf(acc.x, 0.f); acc.y = fmaxf(acc.y, 0.f);
    acc.z = fmaxf(acc.z, 0.f); acc.w = fmaxf(acc.w, 0.f);
    reinterpret_cast<float4*>(out)[(long long)i * 32 + lane] = acc;
}

// ---------------- launch: fork/join across two streams -----------------------
extern "C" void kernel_launch(void* const* d_in, const int* in_sizes, int n_in,
                              void* d_out, int out_size) {
    const float* H  = (const float*)d_in[0];
    const int*   EI = (const int*)d_in[1];
    const float* W  = (const float*)d_in[2];
    const float* B  = (const float*)d_in[3];
    float* out = (float*)d_out;

    static int inited = 0;
    static int have_streams = 0;
    static cudaStream_t sA, sB;
    static cudaEvent_t evRoot, evA, evB;
    if (!inited) {
        cudaFuncSetAttribute(k_gemm, cudaFuncAttributeMaxDynamicSharedMemorySize, SM_TOT);
        if (cudaStreamCreateWithFlags(&sA, cudaStreamNonBlocking) == cudaSuccess &&
            cudaStreamCreateWithFlags(&sB, cudaStreamNonBlocking) == cudaSuccess &&
            cudaEventCreateWithFlags(&evRoot, cudaEventDisableTiming) == cudaSuccess &&
            cudaEventCreateWithFlags(&evA, cudaEventDisableTiming) == cudaSuccess &&
            cudaEventCreateWithFlags(&evB, cudaEventDisableTiming) == cudaSuccess)
            have_streams = 1;
        inited = 1;
    }

    int gather_grid = (NN * 32 + 255) / 256;

    if (have_streams) {
        cudaEventRecord(evRoot, 0);
        cudaStreamWaitEvent(sA, evRoot, 0);
        cudaStreamWaitEvent(sB, evRoot, 0);
        k_prep<<<NBLK, 1024, 0, sA>>>(EI);                    // 1 (A)
        k_wsplit<<<16, 256, 0, sB>>>(W);                      // 2 (B)
        k_hsplit<<<NGRP, 256, 0, sB>>>(H);                    // 3 (B)
        k_gemm<<<GGRID, 256, SM_TOT, sB>>>(B);                // 4 (B) <- profiled
        k_count<<<(NE + 255) / 256, 256, 0, sA>>>(EI);        // 5 (A)
        k_blkscan<<<NBLK, 1024, 0, sA>>>();                   // 6 (A)
        k_apply<<<NBLK, 1024, 0, sA>>>();                     // 7 (A)
        k_fill<<<(NE + 255) / 256, 256, 0, sA>>>(EI);         // 8 (A)
        cudaEventRecord(evA, sA);
        cudaEventRecord(evB, sB);
        cudaStreamWaitEvent(0, evA, 0);
        cudaStreamWaitEvent(0, evB, 0);
        k_gather<<<gather_grid, 256>>>(out);                  // 9 (join)
    } else {
        k_prep<<<NBLK, 1024>>>(EI);
        k_wsplit<<<16, 256>>>(W);
        k_hsplit<<<NGRP, 256>>>(H);
        k_gemm<<<GGRID, 256, SM_TOT>>>(B);
        k_count<<<(NE + 255) / 256, 256>>>(EI);
        k_blkscan<<<NBLK, 1024>>>();
        k_apply<<<NBLK, 1024>>>();
        k_fill<<<(NE + 255) / 256, 256>>>(EI);
        k_gather<<<gather_grid, 256>>>(out);
    }
}

// round 17
// speedup vs baseline: 1.1180x; 1.1180x over previous
#include <cuda_runtime.h>
#include <cuda_fp16.h>
#include <cstdint>

#define NN 100000
#define NE 600000
#define DD 128
#define NBLK 98                         // ceil(NN/1024)
#define NTILE 1563                      // ceil(NN/64) gemm M-tiles
#define GGRID 592                       // 148 SMs x 4 CTAs persistent

// ---------------- scratch (device globals; no allocations allowed) ----------
static __device__ int   g_is64;
static __device__ int   g_deg[NN];
static __device__ float g_dinv[NN];
static __device__ int   g_off[NN + 1];
static __device__ int   g_cur[NN];
static __device__ int   g_col[NE];
static __device__ int   g_bsum[NBLK];
static __device__ __align__(16) unsigned long long g_Wimg[4096]; // 32KB W fp16 image
static __device__ __align__(16) unsigned int g_Hlh[(long long)NN * 64]; // 25.6MB Hl fp16

typedef unsigned long long u64;
typedef unsigned int u32;

__device__ __forceinline__ int edge_at(const int* ei, int is64, int which, int e) {
    if (is64) {
        const long long* p = (const long long*)ei;
        return (int)p[(long long)which * NE + e];
    }
    return ei[which * NE + e];
}

__device__ __forceinline__ u32 pkh(float x, float y) {
    __half2 h = __floats2half2_rn(x, y);
    return *reinterpret_cast<u32*>(&h);
}

// ---------------- chain A-1) dtype sniff (deg zeroed by memsetAsync) ---------
__global__ void k_sniff(const int* __restrict__ ei) {
    __shared__ int nz;
    if (threadIdx.x == 0) nz = 0;
    __syncthreads();
    int acc = 0;
    for (int j = threadIdx.x; j < 1024; j += blockDim.x)
        acc |= ei[2 * j + 1];               // odd words all-zero <=> int64
    if (acc) atomicOr(&nz, 1);
    __syncthreads();
    if (threadIdx.x == 0) g_is64 = (nz == 0) ? 1 : 0;
}

// ---------------- chain B-1) W -> fp16 swizzled smem image -------------------
// off = n*256 + (((kq>>1)^(n&7))<<4) + (kq&1)*8
__global__ void k_wsplit(const float* __restrict__ W) {
    int i = blockIdx.x * blockDim.x + threadIdx.x;
    if (i >= 4096) return;
    int n = i >> 5, kq = i & 31;
    float4 w = reinterpret_cast<const float4*>(W)[n * 32 + kq];
    u64 v = (u64)pkh(w.x, w.y) | ((u64)pkh(w.z, w.w) << 32);
    int off = n * 256 + (((kq >> 1) ^ (n & 7)) << 4) + (kq & 1) * 8;
    *reinterpret_cast<u64*>(reinterpret_cast<char*>(g_Wimg) + off) = v;
}

// ---------------- chain A-2) degree count ------------------------------------
__global__ void k_count(const int* __restrict__ ei) {
    int e = blockIdx.x * blockDim.x + threadIdx.x;
    if (e < NE) {
        int is64 = g_is64;
        int dst = edge_at(ei, is64, 0, e);
        if ((unsigned)dst < NN) atomicAdd(&g_deg[dst], 1);
    }
}

// ======== chain B-2) PERSISTENT GEMM, A staged+converted in smem =============
// Hl(fp16) = H @ W^T + b.  Per-tile: M=64 x N=128 x K=128; warps 2(M) x 4(N).
// B staged once (32KB); A tile (64x128 fp32) read coalesced from H, converted
// to fp16 into 16KB swizzled smem per tile; A frags via ldmatrix.

#define SM_A   32768                    // A tile after B image
#define SM_TOT 49152                    // 32KB B + 16KB A

__device__ __forceinline__ void ldsm_x4(u32& r0, u32& r1, u32& r2, u32& r3, u32 addr) {
    asm volatile("ldmatrix.sync.aligned.m8n8.x4.shared.b16 {%0,%1,%2,%3}, [%4];"
                 : "=r"(r0), "=r"(r1), "=r"(r2), "=r"(r3) : "r"(addr));
}

__device__ __forceinline__ void mma_f16(float* d, const u32* a, const u32* b) {
    asm volatile("mma.sync.aligned.m16n8k16.row.col.f32.f16.f16.f32 "
                 "{%0,%1,%2,%3}, {%4,%5,%6,%7}, {%8,%9}, {%0,%1,%2,%3};"
                 : "+f"(d[0]), "+f"(d[1]), "+f"(d[2]), "+f"(d[3])
                 : "r"(a[0]), "r"(a[1]), "r"(a[2]), "r"(a[3]),
                   "r"(b[0]), "r"(b[1]));
}

__global__ void __launch_bounds__(256, 4)
k_gemm(const float* __restrict__ H,
       const float* __restrict__ B) {
    extern __shared__ char smem[];
    const u32 smem_u32 = (u32)__cvta_generic_to_shared(smem);

    int t = threadIdx.x;

    // ---- stage B once: 32KB copy of precomputed image ----
    {
        const float4* src = reinterpret_cast<const float4*>(g_Wimg);
        float4* dst = reinterpret_cast<float4*>(smem);
#pragma unroll
        for (int i = 0; i < 8; i++)
            dst[t + 256 * i] = src[t + 256 * i];
    }

    int w  = t >> 5;
    int l  = t & 31;
    int wm = w & 1;                     // M half
    int wn = w >> 1;                    // N quarter

    int rowB0 = wn * 32 + (l & 7) + ((l & 16) >> 1);
    int uB_add = ((l >> 3) & 1);
    int rowA0 = wm * 32 + (l & 7) + (l & 8);
    int uA_add = (l >> 4);
    int rq = l >> 2, cq = (l & 3) * 2;

    const float4* H4 = reinterpret_cast<const float4*>(H);

    for (int tile = blockIdx.x; tile < NTILE; tile += GGRID) {
        int r0 = tile * 64;

        // ---- stage A tile: 64x128 fp32 -> fp16 swizzled smem ----
        __syncthreads();                // protect smem A from prev iteration's readers
#pragma unroll
        for (int ii = 0; ii < 8; ii++) {
            int i = t + 256 * ii;       // 0..2047
            int row = i >> 5, kq = i & 31;
            int gr = r0 + row; if (gr >= NN) gr = NN - 1;
            float4 h = H4[(long long)gr * 32 + kq];
            u64 v = (u64)pkh(h.x, h.y) | ((u64)pkh(h.z, h.w) << 32);
            int off = row * 256 + (((kq >> 1) ^ (row & 7)) << 4) + (kq & 1) * 8;
            *reinterpret_cast<u64*>(smem + SM_A + off) = v;
        }
        __syncthreads();

        float d[2][4][4];
#pragma unroll
        for (int a = 0; a < 2; a++)
#pragma unroll
            for (int bq = 0; bq < 4; bq++)
#pragma unroll
                for (int c = 0; c < 4; c++) d[a][bq][c] = 0.0f;

#pragma unroll 2
        for (int ks = 0; ks < 8; ks++) {
            u32 aF[2][4];
#pragma unroll
            for (int mt = 0; mt < 2; mt++) {
                int row = rowA0 + mt * 16;
                int u = 2 * ks + uA_add;
                u32 off = row * 256 + (((u) ^ (row & 7)) << 4);
                ldsm_x4(aF[mt][0], aF[mt][1], aF[mt][2], aF[mt][3],
                        smem_u32 + SM_A + off);
            }
            u32 bF[2][4];
#pragma unroll
            for (int nt = 0; nt < 2; nt++) {
                int row = rowB0 + nt * 16;
                int u = 2 * ks + uB_add;
                u32 off = row * 256 + (((u) ^ (row & 7)) << 4);
                ldsm_x4(bF[nt][0], bF[nt][1], bF[nt][2], bF[nt][3], smem_u32 + off);
            }
#pragma unroll
            for (int mt = 0; mt < 2; mt++)
#pragma unroll
                for (int nt = 0; nt < 2; nt++)
#pragma unroll
                    for (int h = 0; h < 2; h++)
                        mma_f16(d[mt][nt * 2 + h], aF[mt], &bF[nt][h * 2]);
        }

        // ---- epilogue: add bias, store fp16 ----
#pragma unroll
        for (int j = 0; j < 4; j++) {
            int col = wn * 32 + j * 8 + cq;
            float2 bias = *reinterpret_cast<const float2*>(B + col);
            int cp = col >> 1;
#pragma unroll
            for (int mt = 0; mt < 2; mt++) {
                int gr0 = r0 + wm * 32 + mt * 16 + rq;
                float* dd = d[mt][j];
                if (gr0 < NN)
                    g_Hlh[(long long)gr0 * 64 + cp] = pkh(dd[0] + bias.x, dd[1] + bias.y);
                if (gr0 + 8 < NN)
                    g_Hlh[(long long)(gr0 + 8) * 64 + cp] = pkh(dd[2] + bias.x, dd[3] + bias.y);
            }
        }
    }
}

// ---------------- chain A-3) per-block scan ----------------------------------
__global__ void k_blkscan() {
    __shared__ int ws[32];
    int t   = threadIdx.x;
    int i   = blockIdx.x * 1024 + t;
    int lane = t & 31, wid = t >> 5;

    int d = (i < NN) ? g_deg[i] : 0;

    int incl = d;
#pragma unroll
    for (int o = 1; o < 32; o <<= 1) {
        int v = __shfl_up_sync(0xffffffffu, incl, o);
        if (lane >= o) incl += v;
    }
    if (lane == 31) ws[wid] = incl;
    __syncthreads();
    if (wid == 0) {
        int v = ws[lane];
        int s = v;
#pragma unroll
        for (int o = 1; o < 32; o <<= 1) {
            int u = __shfl_up_sync(0xffffffffu, s, o);
            if (lane >= o) s += u;
        }
        ws[lane] = s - v;
    }
    __syncthreads();

    int excl = incl - d + ws[wid];
    if (i < NN) {
        g_off[i]  = excl;
        g_dinv[i] = rsqrtf((float)(d + 1));
    }
    if (t == 1023) g_bsum[blockIdx.x] = excl + d;
}

// ---------------- chain A-4) apply block offsets -----------------------------
__global__ void k_apply() {
    __shared__ int sb[NBLK];
    __shared__ int s_off;
    int t = threadIdx.x, bid = blockIdx.x;
    if (t < NBLK) sb[t] = g_bsum[t];
    __syncthreads();
    if (t == 0) {
        int run = 0;
        for (int b = 0; b < bid; b++) run += sb[b];
        s_off = run;
        if (bid == NBLK - 1) {
            int tot = run;
            for (int b = bid; b < NBLK; b++) tot += sb[b];
            g_off[NN] = tot;
        }
    }
    __syncthreads();
    int i = bid * 1024 + t;
    if (i < NN) {
        int v = g_off[i] + s_off;
        g_off[i] = v;
        g_cur[i] = v;
    }
}

// ---------------- chain A-5) CSR fill ----------------------------------------
__global__ void k_fill(const int* __restrict__ ei) {
    int e = blockIdx.x * blockDim.x + threadIdx.x;
    if (e < NE) {
        int is64 = g_is64;
        int dst = edge_at(ei, is64, 0, e);
        int src = edge_at(ei, is64, 1, e);
        if ((unsigned)dst < NN && (unsigned)src < NN) {
            int p = atomicAdd(&g_cur[dst], 1);
            if ((unsigned)p < NE) g_col[p] = src;
        }
    }
}

// ---------------- join) gather (fp16 src), 4-wide ILP ------------------------
__global__ void k_gather(float* __restrict__ out) {
    int gwarp = (blockIdx.x * blockDim.x + threadIdx.x) >> 5;
    int lane  = threadIdx.x & 31;
    if (gwarp >= NN) return;
    int i = gwarp;

    float di = g_dinv[i];
    const uint2* Hl = reinterpret_cast<const uint2*>(g_Hlh);

    float s2 = di * di;
    uint2 p = Hl[(long long)i * 32 + lane];
    float2 a0 = __half22float2(*reinterpret_cast<__half2*>(&p.x));
    float2 a1 = __half22float2(*reinterpret_cast<__half2*>(&p.y));
    float4 acc;
    acc.x = a0.x * s2; acc.y = a0.y * s2; acc.z = a1.x * s2; acc.w = a1.y * s2;

    int s = g_off[i];
    int e = g_off[i + 1];
    int j = s;
    for (; j + 3 < e; j += 4) {         // 4 independent L2 row streams
        int s0 = g_col[j];
        int s1 = g_col[j + 1];
        int s2i = g_col[j + 2];
        int s3 = g_col[j + 3];
        float n0 = di * g_dinv[s0];
        float n1 = di * g_dinv[s1];
        float n2 = di * g_dinv[s2i];
        float n3 = di * g_dinv[s3];
        uint2 p0 = Hl[(long long)s0 * 32 + lane];
        uint2 p1 = Hl[(long long)s1 * 32 + lane];
        uint2 p2 = Hl[(long long)s2i * 32 + lane];
        uint2 p3 = Hl[(long long)s3 * 32 + lane];
        float2 v00 = __half22float2(*reinterpret_cast<__half2*>(&p0.x));
        float2 v01 = __half22float2(*reinterpret_cast<__half2*>(&p0.y));
        float2 v10 = __half22float2(*reinterpret_cast<__half2*>(&p1.x));
        float2 v11 = __half22float2(*reinterpret_cast<__half2*>(&p1.y));
        float2 v20 = __half22float2(*reinterpret_cast<__half2*>(&p2.x));
        float2 v21 = __half22float2(*reinterpret_cast<__half2*>(&p2.y));
        float2 v30 = __half22float2(*reinterpret_cast<__half2*>(&p3.x));
        float2 v31 = __half22float2(*reinterpret_cast<__half2*>(&p3.y));
        acc.x += v00.x * n0; acc.y += v00.y * n0;
        acc.z += v01.x * n0; acc.w += v01.y * n0;
        acc.x += v10.x * n1; acc.y += v10.y * n1;
        acc.z += v11.x * n1; acc.w += v11.y * n1;
        acc.x += v20.x * n2; acc.y += v20.y * n2;
        acc.z += v21.x * n2; acc.w += v21.y * n2;
        acc.x += v30.x * n3; acc.y += v30.y * n3;
        acc.z += v31.x * n3; acc.w += v31.y * n3;
    }
    for (; j < e; j++) {
        int s0 = g_col[j];
        float n0 = di * g_dinv[s0];
        uint2 p0 = Hl[(long long)s0 * 32 + lane];
        float2 v00 = __half22float2(*reinterpret_cast<__half2*>(&p0.x));
        float2 v01 = __half22float2(*reinterpret_cast<__half2*>(&p0.y));
        acc.x += v00.x * n0; acc.y += v00.y * n0;
        acc.z += v01.x * n0; acc.w += v01.y * n0;
    }

    acc.x = fmaxf(acc.x, 0.f); acc.y = fmaxf(acc.y, 0.f);
    acc.z = fmaxf(acc.z, 0.f); acc.w = fmaxf(acc.w, 0.f);
    reinterpret_cast<float4*>(out)[(long long)i * 32 + lane] = acc;
}

// ---------------- launch: fork/join across two streams -----------------------
extern "C" void kernel_launch(void* const* d_in, const int* in_sizes, int n_in,
                              void* d_out, int out_size) {
    const float* H  = (const float*)d_in[0];
    const int*   EI = (const int*)d_in[1];
    const float* W  = (const float*)d_in[2];
    const float* B  = (const float*)d_in[3];
    float* out = (float*)d_out;

    static int inited = 0;
    static int have_streams = 0;
    static void* deg_addr = nullptr;
    static cudaStream_t sA, sB;
    static cudaEvent_t evRoot, evA, evB;
    if (!inited) {
        cudaFuncSetAttribute(k_gemm, cudaFuncAttributeMaxDynamicSharedMemorySize, SM_TOT);
        cudaGetSymbolAddress(&deg_addr, g_deg);
        if (cudaStreamCreateWithFlags(&sA, cudaStreamNonBlocking) == cudaSuccess &&
            cudaStreamCreateWithFlags(&sB, cudaStreamNonBlocking) == cudaSuccess &&
            cudaEventCreateWithFlags(&evRoot, cudaEventDisableTiming) == cudaSuccess &&
            cudaEventCreateWithFlags(&evA, cudaEventDisableTiming) == cudaSuccess &&
            cudaEventCreateWithFlags(&evB, cudaEventDisableTiming) == cudaSuccess)
            have_streams = 1;
        inited = 1;
    }

    int gather_grid = (NN * 32 + 255) / 256;

    if (have_streams && deg_addr) {
        cudaEventRecord(evRoot, 0);
        cudaStreamWaitEvent(sA, evRoot, 0);
        cudaStreamWaitEvent(sB, evRoot, 0);
        cudaMemsetAsync(deg_addr, 0, NN * sizeof(int), sA);
        k_sniff<<<1, 256, 0, sA>>>(EI);
        k_wsplit<<<16, 256, 0, sB>>>(W);
        k_gemm<<<GGRID, 256, SM_TOT, sB>>>(H, B);             // profiled-ish slot
        k_count<<<(NE + 255) / 256, 256, 0, sA>>>(EI);
        k_blkscan<<<NBLK, 1024, 0, sA>>>();
        k_apply<<<NBLK, 1024, 0, sA>>>();
        k_fill<<<(NE + 255) / 256, 256, 0, sA>>>(EI);
        cudaEventRecord(evA, sA);
        cudaEventRecord(evB, sB);
        cudaStreamWaitEvent(0, evA, 0);
        cudaStreamWaitEvent(0, evB, 0);
        k_gather<<<gather_grid, 256>>>(out);
    } else {
        cudaMemsetAsync(deg_addr, 0, NN * sizeof(int), 0);
        k_sniff<<<1, 256>>>(EI);
        k_wsplit<<<16, 256>>>(W);
        k_gemm<<<GGRID, 256, SM_TOT>>>(H, B);
        k_count<<<(NE + 255) / 256, 256>>>(EI);
        k_blkscan<<<NBLK, 1024>>>();
        k_apply<<<NBLK, 1024>>>();
        k_fill<<<(NE + 255) / 256, 256>>>(EI);
        k_gather<<<gather_grid, 256>>>(out);
    }
}